// round 14
// baseline (speedup 1.0000x reference)
#include <cuda_runtime.h>
#include <cuda_bf16.h>

#define BB 64
#define SS 2048
#define RR 1024
#define HH 512
#define NOWN 8                  // scores owned per thread in softmax prologue
#define NSPLIT 16               // S-chunks in k4 (1024 blocks -> 6.9 waves)
#define SCHUNK (SS / NSPLIT)    // 128
#define BPB 8                   // batches per k1 block
#define RHALF (RR / 2)          // k1 R-split: 512 elements per half

// Scratch (allocation-free rule: __device__ globals)
__device__ float g_att_h[BB * HH];    // 128 KB: half-0 partial + bias
__device__ float g_att_h1[BB * HH];   // 128 KB: half-1 partial
__device__ float g_score[BB * SS];    // 512 KB (raw scores; softmax fused into k4)

__device__ __forceinline__ float fast_tanh(float x) {
    float y;
    asm("tanh.approx.f32 %0, %1;" : "=f"(y) : "f"(x));
    return y;
}

// ---------------------------------------------------------------------------
// K1: att_h[b,j] = dot(h[b,:], W[j,:]) + bias[j]   (+ zero-init of d_out)
// R-SPLIT: grid (HH/8 = 64 j-groups, BB/8 = 8 b-groups, 2 halves) = 1024
// blocks, block 256. Each block computes partial dots over RHALF=512
// elements: h smem 16 KB, 4 W LDG rounds (half the serial L2 chain of the
// unsplit version). Half 0 writes g_att_h (+bias); half 1 writes g_att_h1.
// k2 sums the two buffers in its prologue — no atomics, no init ordering.
// Blocks (by<4, z=0) also zero d_out for k4's red.global accumulation.
// ---------------------------------------------------------------------------
__global__ void k1_att_h(const float* __restrict__ h,
                         const float* __restrict__ W,
                         const float* __restrict__ bias,
                         float* __restrict__ out) {
    const int warp = threadIdx.x >> 5;
    const int lane = threadIdx.x & 31;
    const int j    = blockIdx.x * 8 + warp;
    const int b0   = blockIdx.y * BPB;
    const int half = blockIdx.z;
    const int r0   = half * RHALF;

    // zero d_out: blocks with by = 0..3, z = 0 cover exactly B*R = 65536 floats
    if (blockIdx.y < 4 && half == 0)
        out[((size_t)blockIdx.y * 64 + blockIdx.x) * 256 + threadIdx.x] = 0.f;

    __shared__ float sh[BPB * RHALF];   // 16 KB: 8 h half-rows

    // cooperative fill: 8 rows x 128 float4 = 1024 float4; 256 threads x 4
    const float4* Hg = (const float4*)(h + (size_t)b0 * RR + r0);
#pragma unroll
    for (int k = 0; k < 4; k++) {
        const int li  = threadIdx.x + k * 256;       // 0..1023
        const int row = li >> 7;                     // /128
        const int col = li & 127;
        ((float4*)sh)[row * (RHALF / 4) + col] = Hg[row * (RR / 4) + col];
    }
    __syncthreads();

    const float4* wr = (const float4*)(W + (size_t)j * RR + r0);

    float a[BPB];
#pragma unroll
    for (int k = 0; k < BPB; k++) a[k] = 0.f;

#pragma unroll
    for (int i = 0; i < RHALF / 128; i++) {       // 4 iterations
        const int idx = i * 32 + lane;
        float4 w4 = wr[idx];                       // LDG.128, L2-hot
#pragma unroll
        for (int k = 0; k < BPB; k++) {
            float4 x = ((const float4*)(sh + k * RHALF))[idx];
            a[k] += w4.x * x.x + w4.y * x.y + w4.z * x.z + w4.w * x.w;
        }
    }
#pragma unroll
    for (int o = 16; o; o >>= 1) {
#pragma unroll
        for (int k = 0; k < BPB; k++)
            a[k] += __shfl_down_sync(0xFFFFFFFFu, a[k], o);
    }
    if (lane == 0) {
        if (half == 0) {
            const float bj = bias[j];
#pragma unroll
            for (int k = 0; k < BPB; k++)
                g_att_h[(b0 + k) * HH + j] = a[k] + bj;
        } else {
#pragma unroll
            for (int k = 0; k < BPB; k++)
                g_att_h1[(b0 + k) * HH + j] = a[k];
        }
    }
}

// ---------------------------------------------------------------------------
// K2: score[b,s] = sum_h tanh(p[b,s,h] + att_h[b,h]) * w_alpha[h]
// (b_alpha dropped: a constant shift cancels in softmax)
// grid (B, S/8), block 256 (8 warps, one s per warp). 256 MB streaming read.
// Prologue sums the two k1 half-buffers into s_ah (L2-hot, free).
// tanh via MUFU.TANH so the kernel stays HBM-bound.
// ---------------------------------------------------------------------------
__global__ void k2_scores(const float* __restrict__ p,
                          const float* __restrict__ w_alpha) {
    const int b = blockIdx.x;

    __shared__ float s_ah[HH];
    __shared__ float s_wa[HH];
    for (int i = threadIdx.x; i < HH / 4; i += blockDim.x) {
        float4 u = ((const float4*)(g_att_h  + (size_t)b * HH))[i];
        float4 v = ((const float4*)(g_att_h1 + (size_t)b * HH))[i];
        u.x += v.x; u.y += v.y; u.z += v.z; u.w += v.w;
        ((float4*)s_ah)[i] = u;
        ((float4*)s_wa)[i] = ((const float4*)w_alpha)[i];
    }
    __syncthreads();

    const int warp = threadIdx.x >> 5;
    const int lane = threadIdx.x & 31;
    const int s    = blockIdx.y * 8 + warp;

    const float4* pr = (const float4*)(p + ((size_t)b * SS + s) * HH);

    float acc = 0.f;
#pragma unroll
    for (int i = 0; i < HH / 128; i++) {           // 4 iterations
        float4 p4 = pr[i * 32 + lane];
        int k = (i * 32 + lane) * 4;
        acc += fast_tanh(p4.x + s_ah[k])     * s_wa[k];
        acc += fast_tanh(p4.y + s_ah[k + 1]) * s_wa[k + 1];
        acc += fast_tanh(p4.z + s_ah[k + 2]) * s_wa[k + 2];
        acc += fast_tanh(p4.w + s_ah[k + 3]) * s_wa[k + 3];
    }
#pragma unroll
    for (int o = 16; o; o >>= 1) acc += __shfl_down_sync(0xFFFFFFFFu, acc, o);
    if (lane == 0) g_score[b * SS + s] = acc;
}

// ---------------------------------------------------------------------------
// K4: fused softmax + partial weighted sums over an S-chunk (S-split), with
// direct red.global accumulation into d_out — no reduce kernel.
// grid (B, NSPLIT=16), block 256.
// Prologue: each block redundantly computes its batch row's masked softmax
// into smem (full 8 KB weight row).
// softmax -> *mask -> renorm  ==  e_i*m_i / sum_j(e_j*m_j)  (max-subtracted).
// Main loop: dense 4 KB-row streaming of att_feats (512 MB total).
// ---------------------------------------------------------------------------
__global__ void k4_wsum(const float* __restrict__ feats,
                        const int* __restrict__ mask,
                        float* __restrict__ out) {
    const int b   = blockIdx.x;
    const int sp  = blockIdx.y;
    const int s0  = sp * SCHUNK;
    const int tid = threadIdx.x;

    __shared__ float sw[SS];       // 8 KB: full weight row
    __shared__ float red[8];

    // --- load all SS scores for this batch row: thread tid owns tid + k*256
    float v[NOWN];
    int   m[NOWN];
#pragma unroll
    for (int k = 0; k < NOWN; k++) {
        v[k] = g_score[b * SS + k * 256 + tid];
        m[k] = mask[b * SS + k * 256 + tid];
    }

    // --- block max (over all scores, matching reference stability)
    float mx = v[0];
#pragma unroll
    for (int k = 1; k < NOWN; k++) mx = fmaxf(mx, v[k]);
#pragma unroll
    for (int o = 16; o; o >>= 1) mx = fmaxf(mx, __shfl_xor_sync(0xFFFFFFFFu, mx, o));
    if ((tid & 31) == 0) red[tid >> 5] = mx;
    __syncthreads();
    mx = fmaxf(fmaxf(fmaxf(red[0], red[1]), fmaxf(red[2], red[3])),
               fmaxf(fmaxf(red[4], red[5]), fmaxf(red[6], red[7])));
    __syncthreads();

    // --- masked exponentials + block sum
    float e[NOWN];
    float sum = 0.f;
#pragma unroll
    for (int k = 0; k < NOWN; k++) {
        e[k] = m[k] ? __expf(v[k] - mx) : 0.f;
        sum += e[k];
    }
#pragma unroll
    for (int o = 16; o; o >>= 1) sum += __shfl_xor_sync(0xFFFFFFFFu, sum, o);
    if ((tid & 31) == 0) red[tid >> 5] = sum;
    __syncthreads();
    sum = red[0] + red[1] + red[2] + red[3] + red[4] + red[5] + red[6] + red[7];
    const float inv = 1.f / sum;

#pragma unroll
    for (int k = 0; k < NOWN; k++) sw[k * 256 + tid] = e[k] * inv;
    __syncthreads();

    // --- streaming weighted sum over this block's 128-row chunk
    const float4* base = (const float4*)(feats + ((size_t)b * SS + s0) * RR) + tid;
    const float*  wrow = sw + s0;

    float4 acc = make_float4(0.f, 0.f, 0.f, 0.f);
#pragma unroll 4
    for (int i = 0; i < SCHUNK; i++) {
        float4 f = base[(size_t)i * (RR / 4)];
        float w = wrow[i];
        acc.x += w * f.x; acc.y += w * f.y; acc.z += w * f.z; acc.w += w * f.w;
    }

    // --- accumulate directly into the output (REDG; 16 contributors/address)
    float* o = out + (size_t)b * RR + tid * 4;
    atomicAdd(o + 0, acc.x);
    atomicAdd(o + 1, acc.y);
    atomicAdd(o + 2, acc.z);
    atomicAdd(o + 3, acc.w);
}

// ---------------------------------------------------------------------------
extern "C" void kernel_launch(void* const* d_in, const int* in_sizes, int n_in,
                              void* d_out, int out_size) {
    const float* h         = (const float*)d_in[0];
    const float* att_feats = (const float*)d_in[1];
    const float* p_att     = (const float*)d_in[2];
    const int*   masks     = (const int*)  d_in[3];
    const float* W         = (const float*)d_in[4];
    const float* b_h2att   = (const float*)d_in[5];
    const float* w_alpha   = (const float*)d_in[6];
    // d_in[7] = b_alpha: unused (constant shift cancels in softmax)
    float*       out       = (float*)d_out;

    k1_att_h  <<<dim3(HH / 8, BB / BPB, 2), 256>>>(h, W, b_h2att, out);
    k2_scores <<<dim3(BB, SS / 8),          256>>>(p_att, w_alpha);
    k4_wsum   <<<dim3(BB, NSPLIT),          256>>>(att_feats, masks, out);
}

// round 15
// speedup vs baseline: 1.0238x; 1.0238x over previous
#include <cuda_runtime.h>
#include <cuda_bf16.h>

#define BB 64
#define SS 2048
#define RR 1024
#define HH 512
#define NOWN 8                  // scores owned per thread in softmax prologue
#define NSPLIT 16               // S-chunks in k4 (1024 blocks -> 6.9 waves)
#define SCHUNK (SS / NSPLIT)    // 128
#define BPB 8                   // batches per k1 block

// Scratch (allocation-free rule: __device__ globals)
__device__ float g_att_h[BB * HH];   // 128 KB
__device__ float g_score[BB * SS];   // 512 KB (raw scores; softmax fused into k4)

__device__ __forceinline__ float fast_tanh(float x) {
    float y;
    asm("tanh.approx.f32 %0, %1;" : "=f"(y) : "f"(x));
    return y;
}

// ---------------------------------------------------------------------------
// K1: att_h[b,j] = dot(h[b,:], W[j,:]) + bias[j]   (+ zero-init of d_out)
// R13's proven-best shape (10.9 us): grid (64 j-groups, 8 b-groups), block
// 256. Direct LDG.128 of the L2-hot W row, 8 h rows staged in 32 KB smem,
// 8 independent accumulators per warp. FROZEN — five shapes all plateau
// ~11 us (fixed per-block latency), so this is the keeper.
// First 256 blocks (by < 4) zero d_out for k4's red.global accumulation.
// ---------------------------------------------------------------------------
__global__ void k1_att_h(const float* __restrict__ h,
                         const float* __restrict__ W,
                         const float* __restrict__ bias,
                         float* __restrict__ out) {
    const int warp = threadIdx.x >> 5;
    const int lane = threadIdx.x & 31;
    const int j    = blockIdx.x * 8 + warp;
    const int b0   = blockIdx.y * BPB;

    // zero d_out: blocks with by = 0..3 cover exactly B*R = 65536 floats
    if (blockIdx.y < 4)
        out[((size_t)blockIdx.y * 64 + blockIdx.x) * 256 + threadIdx.x] = 0.f;

    __shared__ float sh[BPB * RR];    // 32 KB: this block's 8 h rows

    const float4* Hg = (const float4*)(h + (size_t)b0 * RR);
#pragma unroll
    for (int k = 0; k < BPB; k++)
        ((float4*)sh)[threadIdx.x + k * 256] = Hg[threadIdx.x + k * 256];

    __syncthreads();

    const float4* wr = (const float4*)(W + (size_t)j * RR);

    float a[BPB];
#pragma unroll
    for (int k = 0; k < BPB; k++) a[k] = 0.f;

#pragma unroll
    for (int i = 0; i < RR / 128; i++) {          // 8 iterations
        const int idx = i * 32 + lane;
        float4 w4 = wr[idx];                       // LDG.128, L2-hot
#pragma unroll
        for (int k = 0; k < BPB; k++) {
            float4 x = ((const float4*)(sh + k * RR))[idx];
            a[k] += w4.x * x.x + w4.y * x.y + w4.z * x.z + w4.w * x.w;
        }
    }
#pragma unroll
    for (int o = 16; o; o >>= 1) {
#pragma unroll
        for (int k = 0; k < BPB; k++)
            a[k] += __shfl_down_sync(0xFFFFFFFFu, a[k], o);
    }
    if (lane == 0) {
        const float bj = bias[j];
#pragma unroll
        for (int k = 0; k < BPB; k++)
            g_att_h[(b0 + k) * HH + j] = a[k] + bj;
    }
}

// ---------------------------------------------------------------------------
// K2: score[b,s] = sum_h tanh(p[b,s,h] + att_h[b,h]) * w_alpha[h]
// (b_alpha dropped: a constant shift cancels in softmax)
// grid (B, S/16), block 256 — each warp now owns TWO s rows (two independent
// 4 KB streams -> double LDG MLP; half the blocks paying the prologue fill).
// tanh via MUFU.TANH so the kernel stays HBM-bound. 256 MB streaming read.
// ---------------------------------------------------------------------------
__global__ void k2_scores(const float* __restrict__ p,
                          const float* __restrict__ w_alpha) {
    const int b = blockIdx.x;

    __shared__ float s_ah[HH];
    __shared__ float s_wa[HH];
    for (int i = threadIdx.x; i < HH / 4; i += blockDim.x) {
        ((float4*)s_ah)[i] = ((const float4*)(g_att_h + (size_t)b * HH))[i];
        ((float4*)s_wa)[i] = ((const float4*)w_alpha)[i];
    }
    __syncthreads();

    const int warp = threadIdx.x >> 5;
    const int lane = threadIdx.x & 31;
    const int s0   = blockIdx.y * 16 + warp * 2;   // this warp's first row

    const float4* pr0 = (const float4*)(p + ((size_t)b * SS + s0)     * HH);
    const float4* pr1 = (const float4*)(p + ((size_t)b * SS + s0 + 1) * HH);

    float acc0 = 0.f, acc1 = 0.f;
#pragma unroll
    for (int i = 0; i < HH / 128; i++) {           // 4 iterations
        const int idx = i * 32 + lane;
        float4 q0 = pr0[idx];
        float4 q1 = pr1[idx];
        const int k = idx * 4;
        const float a0 = s_ah[k],     w0 = s_wa[k];
        const float a1 = s_ah[k + 1], w1 = s_wa[k + 1];
        const float a2 = s_ah[k + 2], w2 = s_wa[k + 2];
        const float a3 = s_ah[k + 3], w3 = s_wa[k + 3];
        acc0 += fast_tanh(q0.x + a0) * w0 + fast_tanh(q0.y + a1) * w1
              + fast_tanh(q0.z + a2) * w2 + fast_tanh(q0.w + a3) * w3;
        acc1 += fast_tanh(q1.x + a0) * w0 + fast_tanh(q1.y + a1) * w1
              + fast_tanh(q1.z + a2) * w2 + fast_tanh(q1.w + a3) * w3;
    }
#pragma unroll
    for (int o = 16; o; o >>= 1) {
        acc0 += __shfl_down_sync(0xFFFFFFFFu, acc0, o);
        acc1 += __shfl_down_sync(0xFFFFFFFFu, acc1, o);
    }
    if (lane == 0) {
        g_score[b * SS + s0]     = acc0;
        g_score[b * SS + s0 + 1] = acc1;
    }
}

// ---------------------------------------------------------------------------
// K4: fused softmax + partial weighted sums over an S-chunk (S-split), with
// direct red.global accumulation into d_out — no reduce kernel.
// grid (B, NSPLIT=16), block 256.
// Prologue: each block redundantly computes its batch row's masked softmax
// into smem (full 8 KB weight row).
// softmax -> *mask -> renorm  ==  e_i*m_i / sum_j(e_j*m_j)  (max-subtracted).
// Main loop: dense 4 KB-row streaming of att_feats (512 MB total), unroll 8
// for deeper LDG batching against DRAM latency.
// ---------------------------------------------------------------------------
__global__ void k4_wsum(const float* __restrict__ feats,
                        const int* __restrict__ mask,
                        float* __restrict__ out) {
    const int b   = blockIdx.x;
    const int sp  = blockIdx.y;
    const int s0  = sp * SCHUNK;
    const int tid = threadIdx.x;

    __shared__ float sw[SS];       // 8 KB: full weight row
    __shared__ float red[8];

    // --- load all SS scores for this batch row: thread tid owns tid + k*256
    float v[NOWN];
    int   m[NOWN];
#pragma unroll
    for (int k = 0; k < NOWN; k++) {
        v[k] = g_score[b * SS + k * 256 + tid];
        m[k] = mask[b * SS + k * 256 + tid];
    }

    // --- block max (over all scores, matching reference stability)
    float mx = v[0];
#pragma unroll
    for (int k = 1; k < NOWN; k++) mx = fmaxf(mx, v[k]);
#pragma unroll
    for (int o = 16; o; o >>= 1) mx = fmaxf(mx, __shfl_xor_sync(0xFFFFFFFFu, mx, o));
    if ((tid & 31) == 0) red[tid >> 5] = mx;
    __syncthreads();
    mx = fmaxf(fmaxf(fmaxf(red[0], red[1]), fmaxf(red[2], red[3])),
               fmaxf(fmaxf(red[4], red[5]), fmaxf(red[6], red[7])));
    __syncthreads();

    // --- masked exponentials + block sum
    float e[NOWN];
    float sum = 0.f;
#pragma unroll
    for (int k = 0; k < NOWN; k++) {
        e[k] = m[k] ? __expf(v[k] - mx) : 0.f;
        sum += e[k];
    }
#pragma unroll
    for (int o = 16; o; o >>= 1) sum += __shfl_xor_sync(0xFFFFFFFFu, sum, o);
    if ((tid & 31) == 0) red[tid >> 5] = sum;
    __syncthreads();
    sum = red[0] + red[1] + red[2] + red[3] + red[4] + red[5] + red[6] + red[7];
    const float inv = 1.f / sum;

#pragma unroll
    for (int k = 0; k < NOWN; k++) sw[k * 256 + tid] = e[k] * inv;
    __syncthreads();

    // --- streaming weighted sum over this block's 128-row chunk
    const float4* base = (const float4*)(feats + ((size_t)b * SS + s0) * RR) + tid;
    const float*  wrow = sw + s0;

    float4 acc = make_float4(0.f, 0.f, 0.f, 0.f);
#pragma unroll 8
    for (int i = 0; i < SCHUNK; i++) {
        float4 f = base[(size_t)i * (RR / 4)];
        float w = wrow[i];
        acc.x += w * f.x; acc.y += w * f.y; acc.z += w * f.z; acc.w += w * f.w;
    }

    // --- accumulate directly into the output (REDG; 16 contributors/address)
    float* o = out + (size_t)b * RR + tid * 4;
    atomicAdd(o + 0, acc.x);
    atomicAdd(o + 1, acc.y);
    atomicAdd(o + 2, acc.z);
    atomicAdd(o + 3, acc.w);
}

// ---------------------------------------------------------------------------
extern "C" void kernel_launch(void* const* d_in, const int* in_sizes, int n_in,
                              void* d_out, int out_size) {
    const float* h         = (const float*)d_in[0];
    const float* att_feats = (const float*)d_in[1];
    const float* p_att     = (const float*)d_in[2];
    const int*   masks     = (const int*)  d_in[3];
    const float* W         = (const float*)d_in[4];
    const float* b_h2att   = (const float*)d_in[5];
    const float* w_alpha   = (const float*)d_in[6];
    // d_in[7] = b_alpha: unused (constant shift cancels in softmax)
    float*       out       = (float*)d_out;

    k1_att_h  <<<dim3(HH / 8, BB / BPB), 256>>>(h, W, b_h2att, out);
    k2_scores <<<dim3(BB, SS / 16),      256>>>(p_att, w_alpha);
    k4_wsum   <<<dim3(BB, NSPLIT),       256>>>(att_feats, masks, out);
}